// round 8
// baseline (speedup 1.0000x reference)
#include <cuda_runtime.h>
#include <cuda_fp16.h>
#include <cstdint>

#define BB 8
#define NN 4096
#define DD 128
#define SCALE 0.08838834764831845f
#define LOG2E 1.4426950408889634f
#define QS (SCALE * LOG2E)

#define BM 128
#define BN 64
#define NT (NN / BN)

typedef unsigned long long u64;

// scratch (no cudaMalloc allowed)
__device__ __half g_kh[(size_t)BB * NN * DD];
__device__ __half g_vh[(size_t)BB * NN * DD];
__device__ __half g_qh[(size_t)BB * NN * DD];
__device__ float  g_o[(size_t)BB * NN * DD];

// ---- attention smem (bytes). K/Q/V pitch 136 halves, P pitch 72 halves ----
#define TBUF 17408
#define PBUF 18432
#define SM_KH 0
#define SM_Q  34816              /* 2 bufs */
#define SM_V  69632              /* 3 bufs */
#define SM_P  121856             /* 2 bufs */
#define SM_LS 158720
#define SM_TOT 159744

// ---- PTX helpers ----
__device__ __forceinline__ uint32_t smem_u32(const void* p) {
    uint32_t a;
    asm("{ .reg .u64 t; cvta.to.shared.u64 t,%1; cvt.u32.u64 %0,t; }" : "=r"(a) : "l"(p));
    return a;
}
__device__ __forceinline__ void ldsmx4(uint32_t* r, uint32_t a) {
    asm volatile("ldmatrix.sync.aligned.m8n8.x4.shared.b16 {%0,%1,%2,%3},[%4];"
                 : "=r"(r[0]), "=r"(r[1]), "=r"(r[2]), "=r"(r[3]) : "r"(a));
}
__device__ __forceinline__ void ldsmx4t(uint32_t* r, uint32_t a) {
    asm volatile("ldmatrix.sync.aligned.m8n8.x4.trans.shared.b16 {%0,%1,%2,%3},[%4];"
                 : "=r"(r[0]), "=r"(r[1]), "=r"(r[2]), "=r"(r[3]) : "r"(a));
}
__device__ __forceinline__ void mma16816(float* c, const uint32_t* a, uint32_t b0, uint32_t b1) {
    asm volatile(
        "mma.sync.aligned.m16n8k16.row.col.f32.f16.f16.f32 "
        "{%0,%1,%2,%3},{%4,%5,%6,%7},{%8,%9},{%0,%1,%2,%3};"
        : "+f"(c[0]), "+f"(c[1]), "+f"(c[2]), "+f"(c[3])
        : "r"(a[0]), "r"(a[1]), "r"(a[2]), "r"(a[3]), "r"(b0), "r"(b1));
}
__device__ __forceinline__ float ex2(float x) {
    float y; asm("ex2.approx.f32 %0,%1;" : "=f"(y) : "f"(x)); return y;
}
__device__ __forceinline__ uint32_t packh2(float lo, float hi) {  // lo -> bits[0:16)
    uint32_t r; asm("cvt.rn.f16x2.f32 %0,%1,%2;" : "=r"(r) : "f"(hi), "f"(lo)); return r;
}
#define CPA16(dst, src) \
    asm volatile("cp.async.cg.shared.global [%0],[%1],16;" :: "r"(dst), "l"(src))
#define CPA_COMMIT() asm volatile("cp.async.commit_group;" ::: "memory")
#define CPA_WAIT0()  asm volatile("cp.async.wait_group 0;" ::: "memory")

// ============================================================================
// Attention, single-sync pipeline:
//  iter j: sync | prefetch QV(j+1) | PV(j-1) | S(j) | P(j)=exp2(S) | cp.wait
// l computed by ones-column MMA (extra n8 tile on warps c2==3): l = P @ 1.
// ============================================================================
__global__ void __launch_bounds__(256, 1)
attn_mma(const __half* __restrict__ khg, const __half* __restrict__ vhg,
         const __half* __restrict__ qhg, float* __restrict__ o) {
    extern __shared__ char smem[];
    const uint32_t sb = smem_u32(smem);
    const int tid = threadIdx.x, lane = tid & 31, wid = tid >> 5;
    const int q = lane & 3, lr = lane >> 2;
    const int b = blockIdx.y, row0 = blockIdx.x * BM;

    const __half* kh_b = khg + ((size_t)b * NN + row0) * DD;
    const __half* vh_b = vhg + (size_t)b * NN * DD;
    const __half* qh_b = qhg + (size_t)b * NN * DD;

    const int rg = wid >> 1, cg = wid & 1;   // S: 4x2 warp grid (32x32)
    const int r2 = wid >> 2, c2 = wid & 3;   // PV: 2x4 warp grid (64x32)

    const int rA = (lane & 7) + (lane & 8), cA = (lane & 16) >> 1;
    const int rB = (lane & 7) + ((lane & 16) >> 1), cB = lane & 8;

    // ldmatrix bases
    uint32_t aKh[2], bQ[2][2], aP[2][4], bVh[3][2];
    #pragma unroll
    for (int mt = 0; mt < 2; ++mt)
        aKh[mt] = sb + SM_KH + 2u * ((32 * rg + 16 * mt + rA) * 136 + cA);
    #pragma unroll
    for (int bf = 0; bf < 2; ++bf)
        #pragma unroll
        for (int bt = 0; bt < 2; ++bt)
            bQ[bf][bt] = sb + SM_Q + bf * TBUF +
                         2u * ((32 * cg + 16 * bt + rB) * 136 + cB);
    #pragma unroll
    for (int bf = 0; bf < 2; ++bf)
        #pragma unroll
        for (int mt = 0; mt < 4; ++mt)
            aP[bf][mt] = sb + SM_P + bf * PBUF +
                         2u * ((64 * r2 + 16 * mt + rA) * 72 + cA);
    #pragma unroll
    for (int bf = 0; bf < 3; ++bf)
        #pragma unroll
        for (int bt = 0; bt < 2; ++bt)
            bVh[bf][bt] = sb + SM_V + bf * TBUF +
                          2u * (rA * 136 + 32 * c2 + 16 * bt + cA);

    const uint32_t onesb = ((lane >> 2) == 0) ? 0x3C003C00u : 0u;  // ones col frag
    const bool lwarp = (c2 == 3);

    // stage K tile (once, LDG->STS)
    #pragma unroll
    for (int t = 0; t < 8; ++t) {
        int c = tid + (t << 8);
        int r = c >> 4, c16 = c & 15;
        *(uint4*)(smem + SM_KH + (uint32_t)(r * 272 + c16 * 16)) =
            *(const uint4*)((const char*)(kh_b + (size_t)r * DD) + c16 * 16);
    }
    // prefetch tile 0 (Q buf0, V buf0)
    #pragma unroll
    for (int t = 0; t < 4; ++t) {
        int c = tid + (t << 8);
        int m = c >> 4, c16 = c & 15;
        uint32_t dof = (uint32_t)(m * 272 + c16 * 16);
        CPA16(sb + SM_Q + dof, (const char*)(qh_b + (size_t)m * DD) + c16 * 16);
        CPA16(sb + SM_V + dof, (const char*)(vh_b + (size_t)m * DD) + c16 * 16);
    }
    CPA_COMMIT();
    CPA_WAIT0();
    __syncthreads();   // K + QV(0) visible

    // K fragments -> registers
    uint32_t khr[2][8][4];
    #pragma unroll
    for (int mt = 0; mt < 2; ++mt)
        #pragma unroll
        for (int ks = 0; ks < 8; ++ks)
            ldsmx4(khr[mt][ks], aKh[mt] + ks * 32);

    float sO[4][4][4], sOl[4][4];
    #pragma unroll
    for (int i = 0; i < 4; ++i) {
        #pragma unroll
        for (int j = 0; j < 4; ++j) {
            sO[i][j][0] = 0.f; sO[i][j][1] = 0.f; sO[i][j][2] = 0.f; sO[i][j][3] = 0.f;
        }
        sOl[i][0] = 0.f; sOl[i][1] = 0.f; sOl[i][2] = 0.f; sOl[i][3] = 0.f;
    }

    for (int jt = 0; jt < NT; ++jt) {
        const int qc = jt & 1, vc = jt % 3, pc = jt & 1;
        if (jt > 0) __syncthreads();   // P(jt-1) + QV(jt) visible

        // prefetch QV(jt+1)
        if (jt + 1 < NT) {
            const int qn = (jt + 1) & 1, vn = (jt + 1) % 3;
            const size_t m1 = (size_t)(jt + 1) * BN;
            #pragma unroll
            for (int t = 0; t < 4; ++t) {
                int c = tid + (t << 8);
                int m = c >> 4, c16 = c & 15;
                uint32_t dof = (uint32_t)(m * 272 + c16 * 16);
                CPA16(sb + SM_Q + qn * TBUF + dof,
                      (const char*)(qh_b + (m1 + m) * DD) + c16 * 16);
                CPA16(sb + SM_V + vn * TBUF + dof,
                      (const char*)(vh_b + (m1 + m) * DD) + c16 * 16);
            }
            CPA_COMMIT();
        }

        // ---- PV(jt-1): O += P @ Vh (+ ones column for l on c2==3) ----
        if (jt > 0) {
            const int pp = (jt - 1) & 1, vp = (jt - 1) % 3;
            #pragma unroll
            for (int ks = 0; ks < 4; ++ks) {
                uint32_t ph[4][4], vh[2][4];
                #pragma unroll
                for (int mt = 0; mt < 4; ++mt) ldsmx4(ph[mt], aP[pp][mt] + ks * 32);
                #pragma unroll
                for (int bt = 0; bt < 2; ++bt) ldsmx4t(vh[bt], bVh[vp][bt] + ks * 4352);
                #pragma unroll
                for (int mt = 0; mt < 4; ++mt) {
                    #pragma unroll
                    for (int nt = 0; nt < 4; ++nt)
                        mma16816(sO[mt][nt], ph[mt],
                                 vh[nt >> 1][2 * (nt & 1)], vh[nt >> 1][2 * (nt & 1) + 1]);
                    if (lwarp) mma16816(sOl[mt], ph[mt], onesb, onesb);
                }
            }
        }

        // ---- S(jt) = Kh @ Qh^T ----
        float sC[2][4][4];
        #pragma unroll
        for (int i = 0; i < 2; ++i)
            #pragma unroll
            for (int j = 0; j < 4; ++j) {
                sC[i][j][0] = 0.f; sC[i][j][1] = 0.f; sC[i][j][2] = 0.f; sC[i][j][3] = 0.f;
            }
        #pragma unroll
        for (int ks = 0; ks < 8; ++ks) {
            uint32_t qf[2][4];
            #pragma unroll
            for (int bt = 0; bt < 2; ++bt) ldsmx4(qf[bt], bQ[qc][bt] + ks * 32);
            #pragma unroll
            for (int mt = 0; mt < 2; ++mt)
                #pragma unroll
                for (int nt = 0; nt < 4; ++nt)
                    mma16816(sC[mt][nt], khr[mt][ks],
                             qf[nt >> 1][2 * (nt & 1)], qf[nt >> 1][2 * (nt & 1) + 1]);
        }

        // ---- P(jt) = exp2(S) fp16 -> smem ----
        #pragma unroll
        for (int mt = 0; mt < 2; ++mt) {
            int rbase = 32 * rg + 16 * mt + lr;
            #pragma unroll
            for (int nt = 0; nt < 4; ++nt) {
                int col = 32 * cg + 8 * nt + 2 * q;
                *(uint32_t*)(smem + SM_P + pc * PBUF + 2u * (rbase * 72 + col)) =
                    packh2(ex2(sC[mt][nt][0]), ex2(sC[mt][nt][1]));
                *(uint32_t*)(smem + SM_P + pc * PBUF + 2u * ((rbase + 8) * 72 + col)) =
                    packh2(ex2(sC[mt][nt][2]), ex2(sC[mt][nt][3]));
            }
        }

        if (jt + 1 < NT) CPA_WAIT0();   // QV(jt+1) arrived (own group)
    }

    // ---- final PV(NT-1) ----
    __syncthreads();
    {
        const int pp = (NT - 1) & 1, vp = (NT - 1) % 3;
        #pragma unroll
        for (int ks = 0; ks < 4; ++ks) {
            uint32_t ph[4][4], vh[2][4];
            #pragma unroll
            for (int mt = 0; mt < 4; ++mt) ldsmx4(ph[mt], aP[pp][mt] + ks * 32);
            #pragma unroll
            for (int bt = 0; bt < 2; ++bt) ldsmx4t(vh[bt], bVh[vp][bt] + ks * 4352);
            #pragma unroll
            for (int mt = 0; mt < 4; ++mt) {
                #pragma unroll
                for (int nt = 0; nt < 4; ++nt)
                    mma16816(sO[mt][nt], ph[mt],
                             vh[nt >> 1][2 * (nt & 1)], vh[nt >> 1][2 * (nt & 1) + 1]);
                if (lwarp) mma16816(sOl[mt], ph[mt], onesb, onesb);
            }
        }
    }

    // ---- l to smem (from c2==3 warps, col 0 of ones tile = q==0 threads) ----
    __syncthreads();
    float* lsum = (float*)(smem + SM_LS);
    if (lwarp && q == 0) {
        #pragma unroll
        for (int mt = 0; mt < 4; ++mt) {
            int ra = 64 * r2 + 16 * mt + lr;
            lsum[ra] = sOl[mt][0];
            lsum[ra + 8] = sOl[mt][2];
        }
    }
    __syncthreads();

    // ---- epilogue: O /= l, store ----
    float* ob = o + ((size_t)b * NN + row0) * DD;
    #pragma unroll
    for (int mt = 0; mt < 4; ++mt) {
        int ra = 64 * r2 + 16 * mt + lr;
        float inva = 1.0f / lsum[ra];
        float invb = 1.0f / lsum[ra + 8];
        #pragma unroll
        for (int nt = 0; nt < 4; ++nt) {
            int col = 32 * c2 + 8 * nt + 2 * q;
            *(float2*)(ob + (size_t)ra * DD + col) =
                make_float2(sO[mt][nt][0] * inva, sO[mt][nt][1] * inva);
            *(float2*)(ob + (size_t)(ra + 8) * DD + col) =
                make_float2(sO[mt][nt][2] * invb, sO[mt][nt][3] * invb);
        }
    }
}

// ============================================================================
// Q -> fp16 (pre-scaled by SCALE*log2e)
// ============================================================================
__global__ void __launch_bounds__(256)
qconv_kernel(const float* __restrict__ qg, __half* __restrict__ qh) {
    int i = blockIdx.x * 256 + threadIdx.x;
    float4 v = ((const float4*)qg)[i];
    ((__half2*)qh)[2 * i]     = __floats2half2_rn(v.x * QS, v.y * QS);
    ((__half2*)qh)[2 * i + 1] = __floats2half2_rn(v.z * QS, v.w * QS);
}

// ============================================================================
// fp16 tensor-core projection GEMM (128x128 CTA tile, K=128 resident)
// ============================================================================
__device__ __forceinline__ void gemm16_core(const float* A, const float* W, int wld,
                                            int row0, int col0, char* smg, uint32_t sb,
                                            int tid, float acc[4][4][4]) {
    #pragma unroll
    for (int it = 0; it < 16; ++it) {
        int f = tid + (it << 8);
        int r = f >> 5, c4 = f & 31;
        float4 v = *(const float4*)(A + (size_t)(row0 + r) * 128 + (c4 << 2));
        uint2 h; h.x = packh2(v.x, v.y); h.y = packh2(v.z, v.w);
        *(uint2*)(smg + (uint32_t)(r * 272 + (c4 << 3))) = h;
    }
    #pragma unroll
    for (int it = 0; it < 16; ++it) {
        int f = tid + (it << 8);
        int k = f >> 5, c4 = f & 31;
        float4 v = *(const float4*)(W + (size_t)k * wld + col0 + (c4 << 2));
        uint2 h; h.x = packh2(v.x, v.y); h.y = packh2(v.z, v.w);
        *(uint2*)(smg + 34816 + (uint32_t)(k * 272 + (c4 << 3))) = h;
    }
    __syncthreads();

    const int lane = tid & 31, wid = tid >> 5;
    const int rw = wid >> 2, cw = wid & 3;
    const int rA = (lane & 7) + (lane & 8), cA = (lane & 16) >> 1;

    uint32_t aBase[4], bBase[2];
    #pragma unroll
    for (int mt = 0; mt < 4; ++mt)
        aBase[mt] = sb + 2u * ((64 * rw + 16 * mt + rA) * 136 + cA);
    #pragma unroll
    for (int bt = 0; bt < 2; ++bt)
        bBase[bt] = sb + 34816 + 2u * (rA * 136 + 32 * cw + 16 * bt + cA);

    #pragma unroll
    for (int i = 0; i < 4; ++i)
        #pragma unroll
        for (int j = 0; j < 4; ++j) {
            acc[i][j][0] = 0.f; acc[i][j][1] = 0.f; acc[i][j][2] = 0.f; acc[i][j][3] = 0.f;
        }
    #pragma unroll
    for (int ks = 0; ks < 8; ++ks) {
        uint32_t a[4][4], bf[2][4];
        #pragma unroll
        for (int mt = 0; mt < 4; ++mt) ldsmx4(a[mt], aBase[mt] + ks * 32);
        #pragma unroll
        for (int bt = 0; bt < 2; ++bt) ldsmx4t(bf[bt], bBase[bt] + ks * 4352);
        #pragma unroll
        for (int mt = 0; mt < 4; ++mt)
            #pragma unroll
            for (int nt = 0; nt < 4; ++nt)
                mma16816(acc[mt][nt], a[mt],
                         bf[nt >> 1][2 * (nt & 1)], bf[nt >> 1][2 * (nt & 1) + 1]);
    }
}

__device__ __forceinline__ uint32_t pack_us2(__half a, __half b) {
    return (uint32_t)__half_as_ushort(a) | ((uint32_t)__half_as_ushort(b) << 16);
}

__global__ void __launch_bounds__(256, 2)
gemm16_kv(const float* __restrict__ A, const float* __restrict__ W,
          const float* __restrict__ bias,
          __half* __restrict__ kh, __half* __restrict__ vh) {
    extern __shared__ char smg[];
    const uint32_t sb = smem_u32(smg);
    const int tid = threadIdx.x, lane = tid & 31, wid = tid >> 5;
    const int q = lane & 3, lr = lane >> 2;
    const int rw = wid >> 2, cw = wid & 3;
    const int row0 = blockIdx.y * 128, col0 = blockIdx.x * 128;

    float acc[4][4][4];
    gemm16_core(A, W, 256, row0, col0, smg, sb, tid, acc);

    __half* dh = (col0 == 0) ? kh : vh;
    #pragma unroll
    for (int mt = 0; mt < 4; ++mt) {
        int r = row0 + 64 * rw + 16 * mt + lr;
        #pragma unroll
        for (int nt = 0; nt < 4; ++nt) {
            int col = 32 * cw + 8 * nt + 2 * q;
            float b0 = bias[col0 + col], b1 = bias[col0 + col + 1];
            *(uint32_t*)(dh + (size_t)r * 128 + col) = pack_us2(
                __float2half_rn(acc[mt][nt][0] + b0), __float2half_rn(acc[mt][nt][1] + b1));
            *(uint32_t*)(dh + (size_t)(r + 8) * 128 + col) = pack_us2(
                __float2half_rn(acc[mt][nt][2] + b0), __float2half_rn(acc[mt][nt][3] + b1));
        }
    }
}

__global__ void __launch_bounds__(256, 2)
gemm16_out(const float* __restrict__ A, const float* __restrict__ W,
           const float* __restrict__ bias, float* __restrict__ C) {
    extern __shared__ char smg[];
    const uint32_t sb = smem_u32(smg);
    const int tid = threadIdx.x, lane = tid & 31, wid = tid >> 5;
    const int q = lane & 3, lr = lane >> 2;
    const int rw = wid >> 2, cw = wid & 3;
    const int row0 = blockIdx.y * 128;

    float acc[4][4][4];
    gemm16_core(A, W, 128, row0, 0, smg, sb, tid, acc);

    #pragma unroll
    for (int mt = 0; mt < 4; ++mt) {
        int r = row0 + 64 * rw + 16 * mt + lr;
        #pragma unroll
        for (int nt = 0; nt < 4; ++nt) {
            int col = 32 * cw + 8 * nt + 2 * q;
            float b0 = bias[col], b1 = bias[col + 1];
            *(float2*)(C + (size_t)r * 128 + col) =
                make_float2(acc[mt][nt][0] + b0, acc[mt][nt][1] + b1);
            *(float2*)(C + (size_t)(r + 8) * 128 + col) =
                make_float2(acc[mt][nt][2] + b0, acc[mt][nt][3] + b1);
        }
    }
}

// ============================================================================
extern "C" void kernel_launch(void* const* d_in, const int* in_sizes, int n_in,
                              void* d_out, int out_size) {
    const float* x   = (const float*)d_in[0];
    const float* qg  = (const float*)d_in[1];
    const float* Wkv = (const float*)d_in[2];
    const float* bkv = (const float*)d_in[3];
    const float* Wp  = (const float*)d_in[4];
    const float* bp  = (const float*)d_in[5];
    float* out = (float*)d_out;

    __half *khp, *vhp, *qhp;
    float* op;
    cudaGetSymbolAddress((void**)&khp, g_kh);
    cudaGetSymbolAddress((void**)&vhp, g_vh);
    cudaGetSymbolAddress((void**)&qhp, g_qh);
    cudaGetSymbolAddress((void**)&op, g_o);

    const int M = BB * NN;
    const int gsm = 2 * 128 * 272;  // 69632 B

    cudaFuncSetAttribute(gemm16_kv,
                         cudaFuncAttributeMaxDynamicSharedMemorySize, gsm);
    cudaFuncSetAttribute(gemm16_out,
                         cudaFuncAttributeMaxDynamicSharedMemorySize, gsm);
    cudaFuncSetAttribute(attn_mma,
                         cudaFuncAttributeMaxDynamicSharedMemorySize, SM_TOT);

    gemm16_kv<<<dim3(2, M / 128), 256, gsm>>>(x, Wkv, bkv, khp, vhp);
    qconv_kernel<<<(M * DD / 4) / 256, 256>>>(qg, qhp);
    attn_mma<<<dim3(NN / BM, BB), 256, SM_TOT>>>(khp, vhp, qhp, op);
    gemm16_out<<<dim3(1, M / 128), 256, gsm>>>(op, Wp, bp, out);
}

// round 9
// speedup vs baseline: 1.0228x; 1.0228x over previous
#include <cuda_runtime.h>
#include <cuda_fp16.h>
#include <cstdint>

#define BB 8
#define NN 4096
#define DD 128
#define SCALE 0.08838834764831845f
#define LOG2E 1.4426950408889634f
#define QS (SCALE * LOG2E)

#define BM 64
#define BN 64
#define NT (NN / BN)

typedef unsigned long long u64;

// scratch (no cudaMalloc allowed)
__device__ __half g_kh[(size_t)BB * NN * DD];
__device__ __half g_vh[(size_t)BB * NN * DD];
__device__ __half g_qh[(size_t)BB * NN * DD];
__device__ float  g_o[(size_t)BB * NN * DD];

// ---- attention smem: Q 2 bufs + V 2 bufs, pitch 136 halves (272B/row) ----
#define TBUF 17408
#define SM_Q 0
#define SM_V 34816
#define SM_TOT 69632

// ---- PTX helpers ----
__device__ __forceinline__ uint32_t smem_u32(const void* p) {
    uint32_t a;
    asm("{ .reg .u64 t; cvta.to.shared.u64 t,%1; cvt.u32.u64 %0,t; }" : "=r"(a) : "l"(p));
    return a;
}
__device__ __forceinline__ void ldsmx4(uint32_t* r, uint32_t a) {
    asm volatile("ldmatrix.sync.aligned.m8n8.x4.shared.b16 {%0,%1,%2,%3},[%4];"
                 : "=r"(r[0]), "=r"(r[1]), "=r"(r[2]), "=r"(r[3]) : "r"(a));
}
__device__ __forceinline__ void ldsmx4t(uint32_t* r, uint32_t a) {
    asm volatile("ldmatrix.sync.aligned.m8n8.x4.trans.shared.b16 {%0,%1,%2,%3},[%4];"
                 : "=r"(r[0]), "=r"(r[1]), "=r"(r[2]), "=r"(r[3]) : "r"(a));
}
__device__ __forceinline__ void mma16816(float* c, const uint32_t* a, uint32_t b0, uint32_t b1) {
    asm volatile(
        "mma.sync.aligned.m16n8k16.row.col.f32.f16.f16.f32 "
        "{%0,%1,%2,%3},{%4,%5,%6,%7},{%8,%9},{%0,%1,%2,%3};"
        : "+f"(c[0]), "+f"(c[1]), "+f"(c[2]), "+f"(c[3])
        : "r"(a[0]), "r"(a[1]), "r"(a[2]), "r"(a[3]), "r"(b0), "r"(b1));
}
__device__ __forceinline__ float ex2(float x) {
    float y; asm("ex2.approx.f32 %0,%1;" : "=f"(y) : "f"(x)); return y;
}
__device__ __forceinline__ uint32_t packh2(float lo, float hi) {  // lo -> bits[0:16)
    uint32_t r; asm("cvt.rn.f16x2.f32 %0,%1,%2;" : "=r"(r) : "f"(hi), "f"(lo)); return r;
}
#define CPA16(dst, src) \
    asm volatile("cp.async.cg.shared.global [%0],[%1],16;" :: "r"(dst), "l"(src))
#define CPA_COMMIT() asm volatile("cp.async.commit_group;" ::: "memory")
#define CPA_WAIT0()  asm volatile("cp.async.wait_group 0;" ::: "memory")

// ============================================================================
// Attention, FA2 register-P layout. CTA = 128 thr / 4 warps, BM=64.
// Warp w owns S-rows [16w,16w+16). S = Kh@Qh^T (full 64 cols per warp),
// P = exp2(S) packed in-register into PV A-fragments, O += P@Vh (all 128 d).
// No P smem, no cross-warp deps; 1 sync/tile for QV double-buffer rotation.
// ============================================================================
__global__ void __launch_bounds__(128, 3)
attn_mma(const __half* __restrict__ khg, const __half* __restrict__ vhg,
         const __half* __restrict__ qhg, float* __restrict__ o) {
    extern __shared__ char smem[];
    const uint32_t sb = smem_u32(smem);
    const int tid = threadIdx.x, lane = tid & 31, wid = tid >> 5;
    const int q = lane & 3, lr = lane >> 2;
    const int b = blockIdx.y, row0 = blockIdx.x * BM;

    const __half* vh_b = vhg + (size_t)b * NN * DD;
    const __half* qh_b = qhg + (size_t)b * NN * DD;

    // ldmatrix lane patterns
    const int rB = (lane & 7) + ((lane & 16) >> 1), cB = lane & 8;   // Q (B, non-trans)
    const int rA = (lane & 7) + (lane & 8), cA = (lane & 16) >> 1;   // V (B, trans)

    // Q base addresses: 4 x4-loads cover all 64 n-cols
    uint32_t bQ[2][4];
    #pragma unroll
    for (int bf = 0; bf < 2; ++bf)
        #pragma unroll
        for (int bt = 0; bt < 4; ++bt)
            bQ[bf][bt] = sb + SM_Q + bf * TBUF + 2u * ((16 * bt + rB) * 136 + cB);
    // V base (per buf); bt/kc offsets added inline
    uint32_t bV[2];
    #pragma unroll
    for (int bf = 0; bf < 2; ++bf)
        bV[bf] = sb + SM_V + bf * TBUF + 2u * (rA * 136 + cA);

    // ---- K fragments direct from gmem (one-time): warp rows [16w,16w+16) ----
    const __half* kw = khg + ((size_t)b * NN + row0 + 16 * wid) * DD;
    uint32_t khr[8][4];
    #pragma unroll
    for (int ks = 0; ks < 8; ++ks) {
        khr[ks][0] = *(const uint32_t*)(kw + (size_t)lr * DD + 16 * ks + 2 * q);
        khr[ks][1] = *(const uint32_t*)(kw + (size_t)(lr + 8) * DD + 16 * ks + 2 * q);
        khr[ks][2] = *(const uint32_t*)(kw + (size_t)lr * DD + 16 * ks + 8 + 2 * q);
        khr[ks][3] = *(const uint32_t*)(kw + (size_t)(lr + 8) * DD + 16 * ks + 8 + 2 * q);
    }

    // prefetch tile 0 (Q,V) into buf 0: 64 rows x 16 chunks of 16B each
    #pragma unroll
    for (int t = 0; t < 8; ++t) {
        int c = tid + (t << 7);
        int m = c >> 4, c16 = c & 15;
        uint32_t dof = (uint32_t)(m * 272 + c16 * 16);
        CPA16(sb + SM_Q + dof, (const char*)(qh_b + (size_t)m * DD) + c16 * 16);
        CPA16(sb + SM_V + dof, (const char*)(vh_b + (size_t)m * DD) + c16 * 16);
    }
    CPA_COMMIT();

    float sO[16][4];   // O: 16 n8-tiles over d=128
    #pragma unroll
    for (int j = 0; j < 16; ++j) {
        sO[j][0] = 0.f; sO[j][1] = 0.f; sO[j][2] = 0.f; sO[j][3] = 0.f;
    }
    float l0 = 0.f, l1 = 0.f;   // partial row sums (rows lr, lr+8), cols ≡ {2q,2q+1} mod 8

    for (int jt = 0; jt < NT; ++jt) {
        const int cur = jt & 1;
        CPA_WAIT0();
        __syncthreads();   // QV(jt) visible; all warps done with buf(jt-1)=buf(jt+1)

        if (jt + 1 < NT) {  // prefetch QV(jt+1) into other buffer
            const int nb = cur ^ 1;
            const size_t m1 = (size_t)(jt + 1) * BN;
            #pragma unroll
            for (int t = 0; t < 8; ++t) {
                int c = tid + (t << 7);
                int m = c >> 4, c16 = c & 15;
                uint32_t dof = (uint32_t)(m * 272 + c16 * 16) + nb * TBUF;
                CPA16(sb + SM_Q + dof, (const char*)(qh_b + (m1 + m) * DD) + c16 * 16);
                CPA16(sb + SM_V + dof, (const char*)(vh_b + (m1 + m) * DD) + c16 * 16);
            }
            CPA_COMMIT();
        }

        // ---- S = Kh @ Qh^T : 16 rows x 64 cols per warp, 8 k-steps ----
        float sC[8][4];
        #pragma unroll
        for (int j = 0; j < 8; ++j) {
            sC[j][0] = 0.f; sC[j][1] = 0.f; sC[j][2] = 0.f; sC[j][3] = 0.f;
        }
        #pragma unroll
        for (int ks = 0; ks < 8; ++ks) {
            uint32_t qf[4][4];
            #pragma unroll
            for (int bt = 0; bt < 4; ++bt) ldsmx4(qf[bt], bQ[cur][bt] + ks * 32);
            #pragma unroll
            for (int j = 0; j < 8; ++j)
                mma16816(sC[j], khr[ks], qf[j >> 1][2 * (j & 1)], qf[j >> 1][2 * (j & 1) + 1]);
        }

        // ---- P = exp2(S): in-register pack into PV A-fragments ----
        uint32_t pa[4][4];
        #pragma unroll
        for (int kc = 0; kc < 4; ++kc) {
            float e0 = ex2(sC[2 * kc][0]), e1 = ex2(sC[2 * kc][1]);
            float e2 = ex2(sC[2 * kc][2]), e3 = ex2(sC[2 * kc][3]);
            float f0 = ex2(sC[2 * kc + 1][0]), f1 = ex2(sC[2 * kc + 1][1]);
            float f2 = ex2(sC[2 * kc + 1][2]), f3 = ex2(sC[2 * kc + 1][3]);
            l0 += (e0 + e1) + (f0 + f1);
            l1 += (e2 + e3) + (f2 + f3);
            pa[kc][0] = packh2(e0, e1);   // row lr,   k = 16kc+2q..+1
            pa[kc][1] = packh2(e2, e3);   // row lr+8
            pa[kc][2] = packh2(f0, f1);   // row lr,   k = 16kc+8+2q..
            pa[kc][3] = packh2(f2, f3);   // row lr+8
        }

        // ---- O += P @ Vh : 16 n8-tiles (d=128), 4 k-steps of 16 ----
        #pragma unroll
        for (int kc = 0; kc < 4; ++kc) {
            uint32_t vbase = bV[cur] + kc * 4352;
            #pragma unroll
            for (int bt = 0; bt < 8; ++bt) {
                uint32_t vf[4];
                ldsmx4t(vf, vbase + bt * 32);
                mma16816(sO[2 * bt], pa[kc], vf[0], vf[1]);
                mma16816(sO[2 * bt + 1], pa[kc], vf[2], vf[3]);
            }
        }
    }

    // ---- quad reduction of row sums (rows owned exclusively by this warp) ----
    l0 += __shfl_xor_sync(0xffffffffu, l0, 1);
    l0 += __shfl_xor_sync(0xffffffffu, l0, 2);
    l1 += __shfl_xor_sync(0xffffffffu, l1, 1);
    l1 += __shfl_xor_sync(0xffffffffu, l1, 2);
    const float inva = 1.0f / l0, invb = 1.0f / l1;

    // ---- epilogue: O /= l, store ----
    float* ob = o + ((size_t)b * NN + row0 + 16 * wid) * DD;
    #pragma unroll
    for (int j = 0; j < 16; ++j) {
        int col = 8 * j + 2 * q;
        *(float2*)(ob + (size_t)lr * DD + col) =
            make_float2(sO[j][0] * inva, sO[j][1] * inva);
        *(float2*)(ob + (size_t)(lr + 8) * DD + col) =
            make_float2(sO[j][2] * invb, sO[j][3] * invb);
    }
}

// ============================================================================
// Q -> fp16 (pre-scaled by SCALE*log2e)
// ============================================================================
__global__ void __launch_bounds__(256)
qconv_kernel(const float* __restrict__ qg, __half* __restrict__ qh) {
    int i = blockIdx.x * 256 + threadIdx.x;
    float4 v = ((const float4*)qg)[i];
    ((__half2*)qh)[2 * i]     = __floats2half2_rn(v.x * QS, v.y * QS);
    ((__half2*)qh)[2 * i + 1] = __floats2half2_rn(v.z * QS, v.w * QS);
}

// ============================================================================
// fp16 tensor-core projection GEMM (128x128 CTA tile, K=128 resident)
// ============================================================================
__device__ __forceinline__ void gemm16_core(const float* A, const float* W, int wld,
                                            int row0, int col0, char* smg, uint32_t sb,
                                            int tid, float acc[4][4][4]) {
    #pragma unroll
    for (int it = 0; it < 16; ++it) {
        int f = tid + (it << 8);
        int r = f >> 5, c4 = f & 31;
        float4 v = *(const float4*)(A + (size_t)(row0 + r) * 128 + (c4 << 2));
        uint2 h; h.x = packh2(v.x, v.y); h.y = packh2(v.z, v.w);
        *(uint2*)(smg + (uint32_t)(r * 272 + (c4 << 3))) = h;
    }
    #pragma unroll
    for (int it = 0; it < 16; ++it) {
        int f = tid + (it << 8);
        int k = f >> 5, c4 = f & 31;
        float4 v = *(const float4*)(W + (size_t)k * wld + col0 + (c4 << 2));
        uint2 h; h.x = packh2(v.x, v.y); h.y = packh2(v.z, v.w);
        *(uint2*)(smg + 34816 + (uint32_t)(k * 272 + (c4 << 3))) = h;
    }
    __syncthreads();

    const int lane = tid & 31, wid = tid >> 5;
    const int rw = wid >> 2, cw = wid & 3;
    const int rA = (lane & 7) + (lane & 8), cA = (lane & 16) >> 1;

    uint32_t aBase[4], bBase[2];
    #pragma unroll
    for (int mt = 0; mt < 4; ++mt)
        aBase[mt] = sb + 2u * ((64 * rw + 16 * mt + rA) * 136 + cA);
    #pragma unroll
    for (int bt = 0; bt < 2; ++bt)
        bBase[bt] = sb + 34816 + 2u * (rA * 136 + 32 * cw + 16 * bt + cA);

    #pragma unroll
    for (int i = 0; i < 4; ++i)
        #pragma unroll
        for (int j = 0; j < 4; ++j) {
            acc[i][j][0] = 0.f; acc[i][j][1] = 0.f; acc[i][j][2] = 0.f; acc[i][j][3] = 0.f;
        }
    #pragma unroll
    for (int ks = 0; ks < 8; ++ks) {
        uint32_t a[4][4], bf[2][4];
        #pragma unroll
        for (int mt = 0; mt < 4; ++mt) ldsmx4(a[mt], aBase[mt] + ks * 32);
        #pragma unroll
        for (int bt = 0; bt < 2; ++bt) ldsmx4t(bf[bt], bBase[bt] + ks * 4352);
        #pragma unroll
        for (int mt = 0; mt < 4; ++mt)
            #pragma unroll
            for (int nt = 0; nt < 4; ++nt)
                mma16816(acc[mt][nt], a[mt],
                         bf[nt >> 1][2 * (nt & 1)], bf[nt >> 1][2 * (nt & 1) + 1]);
    }
}

__device__ __forceinline__ uint32_t pack_us2(__half a, __half b) {
    return (uint32_t)__half_as_ushort(a) | ((uint32_t)__half_as_ushort(b) << 16);
}

__global__ void __launch_bounds__(256, 2)
gemm16_kv(const float* __restrict__ A, const float* __restrict__ W,
          const float* __restrict__ bias,
          __half* __restrict__ kh, __half* __restrict__ vh) {
    extern __shared__ char smg[];
    const uint32_t sb = smem_u32(smg);
    const int tid = threadIdx.x, lane = tid & 31, wid = tid >> 5;
    const int q = lane & 3, lr = lane >> 2;
    const int rw = wid >> 2, cw = wid & 3;
    const int row0 = blockIdx.y * 128, col0 = blockIdx.x * 128;

    float acc[4][4][4];
    gemm16_core(A, W, 256, row0, col0, smg, sb, tid, acc);

    __half* dh = (col0 == 0) ? kh : vh;
    #pragma unroll
    for (int mt = 0; mt < 4; ++mt) {
        int r = row0 + 64 * rw + 16 * mt + lr;
        #pragma unroll
        for (int nt = 0; nt < 4; ++nt) {
            int col = 32 * cw + 8 * nt + 2 * q;
            float b0 = bias[col0 + col], b1 = bias[col0 + col + 1];
            *(uint32_t*)(dh + (size_t)r * 128 + col) = pack_us2(
                __float2half_rn(acc[mt][nt][0] + b0), __float2half_rn(acc[mt][nt][1] + b1));
            *(uint32_t*)(dh + (size_t)(r + 8) * 128 + col) = pack_us2(
                __float2half_rn(acc[mt][nt][2] + b0), __float2half_rn(acc[mt][nt][3] + b1));
        }
    }
}

__global__ void __launch_bounds__(256, 2)
gemm16_out(const float* __restrict__ A, const float* __restrict__ W,
           const float* __restrict__ bias, float* __restrict__ C) {
    extern __shared__ char smg[];
    const uint32_t sb = smem_u32(smg);
    const int tid = threadIdx.x, lane = tid & 31, wid = tid >> 5;
    const int q = lane & 3, lr = lane >> 2;
    const int rw = wid >> 2, cw = wid & 3;
    const int row0 = blockIdx.y * 128;

    float acc[4][4][4];
    gemm16_core(A, W, 128, row0, 0, smg, sb, tid, acc);

    #pragma unroll
    for (int mt = 0; mt < 4; ++mt) {
        int r = row0 + 64 * rw + 16 * mt + lr;
        #pragma unroll
        for (int nt = 0; nt < 4; ++nt) {
            int col = 32 * cw + 8 * nt + 2 * q;
            float b0 = bias[col], b1 = bias[col + 1];
            *(float2*)(C + (size_t)r * 128 + col) =
                make_float2(acc[mt][nt][0] + b0, acc[mt][nt][1] + b1);
            *(float2*)(C + (size_t)(r + 8) * 128 + col) =
                make_float2(acc[mt][nt][2] + b0, acc[mt][nt][3] + b1);
        }
    }
}

// ============================================================================
extern "C" void kernel_launch(void* const* d_in, const int* in_sizes, int n_in,
                              void* d_out, int out_size) {
    const float* x   = (const float*)d_in[0];
    const float* qg  = (const float*)d_in[1];
    const float* Wkv = (const float*)d_in[2];
    const float* bkv = (const float*)d_in[3];
    const float* Wp  = (const float*)d_in[4];
    const float* bp  = (const float*)d_in[5];
    float* out = (float*)d_out;

    __half *khp, *vhp, *qhp;
    float* op;
    cudaGetSymbolAddress((void**)&khp, g_kh);
    cudaGetSymbolAddress((void**)&vhp, g_vh);
    cudaGetSymbolAddress((void**)&qhp, g_qh);
    cudaGetSymbolAddress((void**)&op, g_o);

    const int M = BB * NN;
    const int gsm = 2 * 128 * 272;  // 69632 B

    cudaFuncSetAttribute(gemm16_kv,
                         cudaFuncAttributeMaxDynamicSharedMemorySize, gsm);
    cudaFuncSetAttribute(gemm16_out,
                         cudaFuncAttributeMaxDynamicSharedMemorySize, gsm);
    cudaFuncSetAttribute(attn_mma,
                         cudaFuncAttributeMaxDynamicSharedMemorySize, SM_TOT);

    gemm16_kv<<<dim3(2, M / 128), 256, gsm>>>(x, Wkv, bkv, khp, vhp);
    qconv_kernel<<<(M * DD / 4) / 256, 256>>>(qg, qhp);
    attn_mma<<<dim3(NN / BM, BB), 128, SM_TOT>>>(khp, vhp, qhp, op);
    gemm16_out<<<dim3(1, M / 128), 256, gsm>>>(op, Wp, bp, out);
}

// round 10
// speedup vs baseline: 1.1360x; 1.1108x over previous
#include <cuda_runtime.h>
#include <cuda_fp16.h>
#include <cstdint>

#define BB 8
#define NN 4096
#define DD 128
#define SCALE 0.08838834764831845f
#define LOG2E 1.4426950408889634f
#define QS (SCALE * LOG2E)

#define BM 128
#define BN 64
#define NT (NN / BN)

typedef unsigned long long u64;

// scratch (no cudaMalloc allowed)
__device__ __half g_kh[(size_t)BB * NN * DD];
__device__ __half g_vh[(size_t)BB * NN * DD];
__device__ __half g_qh[(size_t)BB * NN * DD];
__device__ float  g_o[(size_t)BB * NN * DD];

// ---- attention smem (bytes). K/Q/V pitch 136 halves (272B), P pitch 72 ----
// K resident 34816 | Q 1 buf 17408 | V 2 bufs 34816 | P 18432 | lsum 1KB
#define SM_K  0
#define SM_Q  34816
#define SM_V  52224
#define TBUF  17408
#define SM_P  87040
#define SM_LS 105472
#define SM_TOT 106496

// ---- PTX helpers ----
__device__ __forceinline__ uint32_t smem_u32(const void* p) {
    uint32_t a;
    asm("{ .reg .u64 t; cvta.to.shared.u64 t,%1; cvt.u32.u64 %0,t; }" : "=r"(a) : "l"(p));
    return a;
}
__device__ __forceinline__ void ldsmx4(uint32_t* r, uint32_t a) {
    asm volatile("ldmatrix.sync.aligned.m8n8.x4.shared.b16 {%0,%1,%2,%3},[%4];"
                 : "=r"(r[0]), "=r"(r[1]), "=r"(r[2]), "=r"(r[3]) : "r"(a));
}
__device__ __forceinline__ void ldsmx4t(uint32_t* r, uint32_t a) {
    asm volatile("ldmatrix.sync.aligned.m8n8.x4.trans.shared.b16 {%0,%1,%2,%3},[%4];"
                 : "=r"(r[0]), "=r"(r[1]), "=r"(r[2]), "=r"(r[3]) : "r"(a));
}
__device__ __forceinline__ void mma16816(float* c, const uint32_t* a, uint32_t b0, uint32_t b1) {
    asm volatile(
        "mma.sync.aligned.m16n8k16.row.col.f32.f16.f16.f32 "
        "{%0,%1,%2,%3},{%4,%5,%6,%7},{%8,%9},{%0,%1,%2,%3};"
        : "+f"(c[0]), "+f"(c[1]), "+f"(c[2]), "+f"(c[3])
        : "r"(a[0]), "r"(a[1]), "r"(a[2]), "r"(a[3]), "r"(b0), "r"(b1));
}
__device__ __forceinline__ float ex2(float x) {
    float y; asm("ex2.approx.f32 %0,%1;" : "=f"(y) : "f"(x)); return y;
}
__device__ __forceinline__ uint32_t packh2(float lo, float hi) {  // lo -> bits[0:16)
    uint32_t r; asm("cvt.rn.f16x2.f32 %0,%1,%2;" : "=r"(r) : "f"(hi), "f"(lo)); return r;
}
#define CPA16(dst, src) \
    asm volatile("cp.async.cg.shared.global [%0],[%1],16;" :: "r"(dst), "l"(src))
#define CPA_COMMIT() asm volatile("cp.async.commit_group;" ::: "memory")
#define CPA_WAIT0()  asm volatile("cp.async.wait_group 0;" ::: "memory")

// ============================================================================
// Attention: BM=128, 8 warps, P via smem, 2 CTAs/SM for cross-CTA overlap.
// Per tile: S(jt) | exp->P | sync1 | cp.async QV(jt+1) | PV(jt) | wait | sync2
// ============================================================================
__global__ void __launch_bounds__(256, 2)
attn_mma(const __half* __restrict__ khg, const __half* __restrict__ vhg,
         const __half* __restrict__ qhg, float* __restrict__ o) {
    extern __shared__ char smem[];
    const uint32_t sb = smem_u32(smem);
    const int tid = threadIdx.x, lane = tid & 31, wid = tid >> 5;
    const int q = lane & 3, lr = lane >> 2;
    const int b = blockIdx.y, row0 = blockIdx.x * BM;

    const __half* kh_b = khg + ((size_t)b * NN + row0) * DD;
    const __half* vh_b = vhg + (size_t)b * NN * DD;
    const __half* qh_b = qhg + (size_t)b * NN * DD;

    const int rg = wid >> 1, cg = wid & 1;   // S: 4x2 warp grid (32x32)
    const int r2 = wid >> 2, c2 = wid & 3;   // PV: 2x4 warp grid (64x32)

    const int rA = (lane & 7) + (lane & 8), cA = (lane & 16) >> 1;   // A/P/V pattern
    const int rB = (lane & 7) + ((lane & 16) >> 1), cB = lane & 8;   // B (Q) pattern

    // ldmatrix bases
    uint32_t aK[2], bQ[2], aP[4], bV[2][2];
    #pragma unroll
    for (int mt = 0; mt < 2; ++mt)
        aK[mt] = sb + SM_K + 2u * ((32 * rg + 16 * mt + rA) * 136 + cA);
    #pragma unroll
    for (int bt = 0; bt < 2; ++bt)
        bQ[bt] = sb + SM_Q + 2u * ((32 * cg + 16 * bt + rB) * 136 + cB);
    #pragma unroll
    for (int mt = 0; mt < 4; ++mt)
        aP[mt] = sb + SM_P + 2u * ((64 * r2 + 16 * mt + rA) * 72 + cA);
    #pragma unroll
    for (int bf = 0; bf < 2; ++bf)
        #pragma unroll
        for (int bt = 0; bt < 2; ++bt)
            bV[bf][bt] = sb + SM_V + bf * TBUF +
                         2u * (rA * 136 + 32 * c2 + 16 * bt + cA);

    // stage K tile (resident for whole kernel)
    #pragma unroll
    for (int t = 0; t < 8; ++t) {
        int c = tid + (t << 8);
        int r = c >> 4, c16 = c & 15;
        *(uint4*)(smem + SM_K + (uint32_t)(r * 272 + c16 * 16)) =
            *(const uint4*)((const char*)(kh_b + (size_t)r * DD) + c16 * 16);
    }
    // prefetch tile 0 (Q, V buf0)
    #pragma unroll
    for (int t = 0; t < 4; ++t) {
        int c = tid + (t << 8);
        int m = c >> 4, c16 = c & 15;
        uint32_t dof = (uint32_t)(m * 272 + c16 * 16);
        CPA16(sb + SM_Q + dof, (const char*)(qh_b + (size_t)m * DD) + c16 * 16);
        CPA16(sb + SM_V + dof, (const char*)(vh_b + (size_t)m * DD) + c16 * 16);
    }
    CPA_COMMIT();
    CPA_WAIT0();
    __syncthreads();   // K + Q(0) + V(0) visible

    float sO[4][4][4];
    #pragma unroll
    for (int i = 0; i < 4; ++i)
        #pragma unroll
        for (int j = 0; j < 4; ++j) {
            sO[i][j][0] = 0.f; sO[i][j][1] = 0.f; sO[i][j][2] = 0.f; sO[i][j][3] = 0.f;
        }
    float lloc[4] = {0.f, 0.f, 0.f, 0.f};

    for (int jt = 0; jt < NT; ++jt) {
        const int vc = jt & 1;

        // ---- S(jt) = K @ Q^T : 32x32 warp tile, 8 k-steps (K ldsm'd per tile) ----
        float sC[2][4][4];
        #pragma unroll
        for (int i = 0; i < 2; ++i)
            #pragma unroll
            for (int j = 0; j < 4; ++j) {
                sC[i][j][0] = 0.f; sC[i][j][1] = 0.f; sC[i][j][2] = 0.f; sC[i][j][3] = 0.f;
            }
        #pragma unroll
        for (int ks = 0; ks < 8; ++ks) {
            uint32_t kf[2][4], qf[2][4];
            #pragma unroll
            for (int mt = 0; mt < 2; ++mt) ldsmx4(kf[mt], aK[mt] + ks * 32);
            #pragma unroll
            for (int bt = 0; bt < 2; ++bt) ldsmx4(qf[bt], bQ[bt] + ks * 32);
            #pragma unroll
            for (int mt = 0; mt < 2; ++mt)
                #pragma unroll
                for (int nt = 0; nt < 4; ++nt)
                    mma16816(sC[mt][nt], kf[mt],
                             qf[nt >> 1][2 * (nt & 1)], qf[nt >> 1][2 * (nt & 1) + 1]);
        }

        // ---- P(jt) = exp2(S) fp16 -> smem; accumulate row sums ----
        #pragma unroll
        for (int mt = 0; mt < 2; ++mt) {
            int rbase = 32 * rg + 16 * mt + lr;
            #pragma unroll
            for (int nt = 0; nt < 4; ++nt) {
                int col = 32 * cg + 8 * nt + 2 * q;
                float p0 = ex2(sC[mt][nt][0]), p1 = ex2(sC[mt][nt][1]);
                float p2 = ex2(sC[mt][nt][2]), p3 = ex2(sC[mt][nt][3]);
                lloc[2 * mt] += p0 + p1;
                lloc[2 * mt + 1] += p2 + p3;
                *(uint32_t*)(smem + SM_P + 2u * (rbase * 72 + col)) = packh2(p0, p1);
                *(uint32_t*)(smem + SM_P + 2u * ((rbase + 8) * 72 + col)) = packh2(p2, p3);
            }
        }
        __syncthreads();   // P visible; Q(jt) fully consumed by all warps

        // prefetch Q(jt+1) into the single Q buf, V(jt+1) into other V buf
        if (jt + 1 < NT) {
            const size_t m1 = (size_t)(jt + 1) * BN;
            #pragma unroll
            for (int t = 0; t < 4; ++t) {
                int c = tid + (t << 8);
                int m = c >> 4, c16 = c & 15;
                uint32_t dof = (uint32_t)(m * 272 + c16 * 16);
                CPA16(sb + SM_Q + dof,
                      (const char*)(qh_b + (m1 + m) * DD) + c16 * 16);
                CPA16(sb + SM_V + (vc ^ 1) * TBUF + dof,
                      (const char*)(vh_b + (m1 + m) * DD) + c16 * 16);
            }
            CPA_COMMIT();
        }

        // ---- PV(jt): O += P @ V(buf vc) : 64x32 warp tile, 4 k-steps ----
        #pragma unroll
        for (int ks = 0; ks < 4; ++ks) {
            uint32_t ph[4][4], vf[2][4];
            #pragma unroll
            for (int mt = 0; mt < 4; ++mt) ldsmx4(ph[mt], aP[mt] + ks * 32);
            #pragma unroll
            for (int bt = 0; bt < 2; ++bt) ldsmx4t(vf[bt], bV[vc][bt] + ks * 4352);
            #pragma unroll
            for (int mt = 0; mt < 4; ++mt)
                #pragma unroll
                for (int nt = 0; nt < 4; ++nt)
                    mma16816(sO[mt][nt], ph[mt],
                             vf[nt >> 1][2 * (nt & 1)], vf[nt >> 1][2 * (nt & 1) + 1]);
        }

        if (jt + 1 < NT) CPA_WAIT0();
        __syncthreads();   // PV(jt) done in all warps; QV(jt+1) arrived
    }

    // ---- l reduction: quad shfl + cross-colgroup via smem ----
    #pragma unroll
    for (int i = 0; i < 4; ++i) {
        lloc[i] += __shfl_xor_sync(0xffffffffu, lloc[i], 1);
        lloc[i] += __shfl_xor_sync(0xffffffffu, lloc[i], 2);
    }
    float* lsum = (float*)(smem + SM_LS);
    if (q == 0) {
        #pragma unroll
        for (int i = 0; i < 4; ++i) {
            int row = 32 * rg + 16 * (i >> 1) + 8 * (i & 1) + lr;
            lsum[cg * 128 + row] = lloc[i];
        }
    }
    __syncthreads();

    // ---- epilogue: O /= l, store ----
    float* ob = o + ((size_t)b * NN + row0) * DD;
    #pragma unroll
    for (int mt = 0; mt < 4; ++mt) {
        int ra = 64 * r2 + 16 * mt + lr;
        float inva = 1.0f / (lsum[ra] + lsum[128 + ra]);
        float invb = 1.0f / (lsum[ra + 8] + lsum[128 + ra + 8]);
        #pragma unroll
        for (int nt = 0; nt < 4; ++nt) {
            int col = 32 * c2 + 8 * nt + 2 * q;
            *(float2*)(ob + (size_t)ra * DD + col) =
                make_float2(sO[mt][nt][0] * inva, sO[mt][nt][1] * inva);
            *(float2*)(ob + (size_t)(ra + 8) * DD + col) =
                make_float2(sO[mt][nt][2] * invb, sO[mt][nt][3] * invb);
        }
    }
}

// ============================================================================
// Q -> fp16 (pre-scaled by SCALE*log2e)
// ============================================================================
__global__ void __launch_bounds__(256)
qconv_kernel(const float* __restrict__ qg, __half* __restrict__ qh) {
    int i = blockIdx.x * 256 + threadIdx.x;
    float4 v = ((const float4*)qg)[i];
    ((__half2*)qh)[2 * i]     = __floats2half2_rn(v.x * QS, v.y * QS);
    ((__half2*)qh)[2 * i + 1] = __floats2half2_rn(v.z * QS, v.w * QS);
}

// ============================================================================
// fp16 tensor-core projection GEMM (128x128 CTA tile, K=128 resident)
// ============================================================================
__device__ __forceinline__ void gemm16_core(const float* A, const float* W, int wld,
                                            int row0, int col0, char* smg, uint32_t sb,
                                            int tid, float acc[4][4][4]) {
    #pragma unroll
    for (int it = 0; it < 16; ++it) {
        int f = tid + (it << 8);
        int r = f >> 5, c4 = f & 31;
        float4 v = *(const float4*)(A + (size_t)(row0 + r) * 128 + (c4 << 2));
        uint2 h; h.x = packh2(v.x, v.y); h.y = packh2(v.z, v.w);
        *(uint2*)(smg + (uint32_t)(r * 272 + (c4 << 3))) = h;
    }
    #pragma unroll
    for (int it = 0; it < 16; ++it) {
        int f = tid + (it << 8);
        int k = f >> 5, c4 = f & 31;
        float4 v = *(const float4*)(W + (size_t)k * wld + col0 + (c4 << 2));
        uint2 h; h.x = packh2(v.x, v.y); h.y = packh2(v.z, v.w);
        *(uint2*)(smg + 34816 + (uint32_t)(k * 272 + (c4 << 3))) = h;
    }
    __syncthreads();

    const int lane = tid & 31, wid = tid >> 5;
    const int rw = wid >> 2, cw = wid & 3;
    const int rA = (lane & 7) + (lane & 8), cA = (lane & 16) >> 1;

    uint32_t aBase[4], bBase[2];
    #pragma unroll
    for (int mt = 0; mt < 4; ++mt)
        aBase[mt] = sb + 2u * ((64 * rw + 16 * mt + rA) * 136 + cA);
    #pragma unroll
    for (int bt = 0; bt < 2; ++bt)
        bBase[bt] = sb + 34816 + 2u * (rA * 136 + 32 * cw + 16 * bt + cA);

    #pragma unroll
    for (int i = 0; i < 4; ++i)
        #pragma unroll
        for (int j = 0; j < 4; ++j) {
            acc[i][j][0] = 0.f; acc[i][j][1] = 0.f; acc[i][j][2] = 0.f; acc[i][j][3] = 0.f;
        }
    #pragma unroll
    for (int ks = 0; ks < 8; ++ks) {
        uint32_t a[4][4], bf[2][4];
        #pragma unroll
        for (int mt = 0; mt < 4; ++mt) ldsmx4(a[mt], aBase[mt] + ks * 32);
        #pragma unroll
        for (int bt = 0; bt < 2; ++bt) ldsmx4t(bf[bt], bBase[bt] + ks * 4352);
        #pragma unroll
        for (int mt = 0; mt < 4; ++mt)
            #pragma unroll
            for (int nt = 0; nt < 4; ++nt)
                mma16816(acc[mt][nt], a[mt],
                         bf[nt >> 1][2 * (nt & 1)], bf[nt >> 1][2 * (nt & 1) + 1]);
    }
}

__device__ __forceinline__ uint32_t pack_us2(__half a, __half b) {
    return (uint32_t)__half_as_ushort(a) | ((uint32_t)__half_as_ushort(b) << 16);
}

__global__ void __launch_bounds__(256, 2)
gemm16_kv(const float* __restrict__ A, const float* __restrict__ W,
          const float* __restrict__ bias,
          __half* __restrict__ kh, __half* __restrict__ vh) {
    extern __shared__ char smg[];
    const uint32_t sb = smem_u32(smg);
    const int tid = threadIdx.x, lane = tid & 31, wid = tid >> 5;
    const int q = lane & 3, lr = lane >> 2;
    const int rw = wid >> 2, cw = wid & 3;
    const int row0 = blockIdx.y * 128, col0 = blockIdx.x * 128;

    float acc[4][4][4];
    gemm16_core(A, W, 256, row0, col0, smg, sb, tid, acc);

    __half* dh = (col0 == 0) ? kh : vh;
    #pragma unroll
    for (int mt = 0; mt < 4; ++mt) {
        int r = row0 + 64 * rw + 16 * mt + lr;
        #pragma unroll
        for (int nt = 0; nt < 4; ++nt) {
            int col = 32 * cw + 8 * nt + 2 * q;
            float b0 = bias[col0 + col], b1 = bias[col0 + col + 1];
            *(uint32_t*)(dh + (size_t)r * 128 + col) = pack_us2(
                __float2half_rn(acc[mt][nt][0] + b0), __float2half_rn(acc[mt][nt][1] + b1));
            *(uint32_t*)(dh + (size_t)(r + 8) * 128 + col) = pack_us2(
                __float2half_rn(acc[mt][nt][2] + b0), __float2half_rn(acc[mt][nt][3] + b1));
        }
    }
}

__global__ void __launch_bounds__(256, 2)
gemm16_out(const float* __restrict__ A, const float* __restrict__ W,
           const float* __restrict__ bias, float* __restrict__ C) {
    extern __shared__ char smg[];
    const uint32_t sb = smem_u32(smg);
    const int tid = threadIdx.x, lane = tid & 31, wid = tid >> 5;
    const int q = lane & 3, lr = lane >> 2;
    const int rw = wid >> 2, cw = wid & 3;
    const int row0 = blockIdx.y * 128;

    float acc[4][4][4];
    gemm16_core(A, W, 128, row0, 0, smg, sb, tid, acc);

    #pragma unroll
    for (int mt = 0; mt < 4; ++mt) {
        int r = row0 + 64 * rw + 16 * mt + lr;
        #pragma unroll
        for (int nt = 0; nt < 4; ++nt) {
            int col = 32 * cw + 8 * nt + 2 * q;
            float b0 = bias[col], b1 = bias[col + 1];
            *(float2*)(C + (size_t)r * 128 + col) =
                make_float2(acc[mt][nt][0] + b0, acc[mt][nt][1] + b1);
            *(float2*)(C + (size_t)(r + 8) * 128 + col) =
                make_float2(acc[mt][nt][2] + b0, acc[mt][nt][3] + b1);
        }
    }
}

// ============================================================================
extern "C" void kernel_launch(void* const* d_in, const int* in_sizes, int n_in,
                              void* d_out, int out_size) {
    const float* x   = (const float*)d_in[0];
    const float* qg  = (const float*)d_in[1];
    const float* Wkv = (const float*)d_in[2];
    const float* bkv = (const float*)d_in[3];
    const float* Wp  = (const float*)d_in[4];
    const float* bp  = (const float*)d_in[5];
    float* out = (float*)d_out;

    __half *khp, *vhp, *qhp;
    float* op;
    cudaGetSymbolAddress((void**)&khp, g_kh);
    cudaGetSymbolAddress((void**)&vhp, g_vh);
    cudaGetSymbolAddress((void**)&qhp, g_qh);
    cudaGetSymbolAddress((void**)&op, g_o);

    const int M = BB * NN;
    const int gsm = 2 * 128 * 272;  // 69632 B

    cudaFuncSetAttribute(gemm16_kv,
                         cudaFuncAttributeMaxDynamicSharedMemorySize, gsm);
    cudaFuncSetAttribute(gemm16_out,
                         cudaFuncAttributeMaxDynamicSharedMemorySize, gsm);
    cudaFuncSetAttribute(attn_mma,
                         cudaFuncAttributeMaxDynamicSharedMemorySize, SM_TOT);

    gemm16_kv<<<dim3(2, M / 128), 256, gsm>>>(x, Wkv, bkv, khp, vhp);
    qconv_kernel<<<(M * DD / 4) / 256, 256>>>(qg, qhp);
    attn_mma<<<dim3(NN / BM, BB), 256, SM_TOT>>>(khp, vhp, qhp, op);
    gemm16_out<<<dim3(1, M / 128), 256, gsm>>>(op, Wp, bp, out);
}

// round 11
// speedup vs baseline: 1.1559x; 1.0175x over previous
#include <cuda_runtime.h>
#include <cuda_fp16.h>
#include <cstdint>

#define BB 8
#define NN 4096
#define DD 128
#define SCALE 0.08838834764831845f
#define LOG2E 1.4426950408889634f
#define QS (SCALE * LOG2E)

#define BM 128
#define BN 64
#define NT (NN / BN)

typedef unsigned long long u64;

// scratch (no cudaMalloc allowed)
__device__ __half g_kh[(size_t)BB * NN * DD];
__device__ __half g_vh[(size_t)BB * NN * DD];
__device__ __half g_qh[(size_t)BB * NN * DD];

// ---- attention smem (bytes). K/Q/V pitch 136 halves (272B), P pitch 72 ----
// K resident 34816 | Q 1 buf 17408 | V 2 bufs 34816 | P 18432 | lsum 1KB
// epilogue reuse: O fp16 -> SM_K region, Wp fp16 -> SM_Q region
#define SM_K  0
#define SM_Q  34816
#define SM_V  52224
#define TBUF  17408
#define SM_P  87040
#define SM_LS 105472
#define SM_TOT 106496

// ---- PTX helpers ----
__device__ __forceinline__ uint32_t smem_u32(const void* p) {
    uint32_t a;
    asm("{ .reg .u64 t; cvta.to.shared.u64 t,%1; cvt.u32.u64 %0,t; }" : "=r"(a) : "l"(p));
    return a;
}
__device__ __forceinline__ void ldsmx4(uint32_t* r, uint32_t a) {
    asm volatile("ldmatrix.sync.aligned.m8n8.x4.shared.b16 {%0,%1,%2,%3},[%4];"
                 : "=r"(r[0]), "=r"(r[1]), "=r"(r[2]), "=r"(r[3]) : "r"(a));
}
__device__ __forceinline__ void ldsmx4t(uint32_t* r, uint32_t a) {
    asm volatile("ldmatrix.sync.aligned.m8n8.x4.trans.shared.b16 {%0,%1,%2,%3},[%4];"
                 : "=r"(r[0]), "=r"(r[1]), "=r"(r[2]), "=r"(r[3]) : "r"(a));
}
__device__ __forceinline__ void mma16816(float* c, const uint32_t* a, uint32_t b0, uint32_t b1) {
    asm volatile(
        "mma.sync.aligned.m16n8k16.row.col.f32.f16.f16.f32 "
        "{%0,%1,%2,%3},{%4,%5,%6,%7},{%8,%9},{%0,%1,%2,%3};"
        : "+f"(c[0]), "+f"(c[1]), "+f"(c[2]), "+f"(c[3])
        : "r"(a[0]), "r"(a[1]), "r"(a[2]), "r"(a[3]), "r"(b0), "r"(b1));
}
__device__ __forceinline__ float ex2(float x) {
    float y; asm("ex2.approx.f32 %0,%1;" : "=f"(y) : "f"(x)); return y;
}
__device__ __forceinline__ uint32_t packh2(float lo, float hi) {  // lo -> bits[0:16)
    uint32_t r; asm("cvt.rn.f16x2.f32 %0,%1,%2;" : "=r"(r) : "f"(hi), "f"(lo)); return r;
}
#define CPA16(dst, src) \
    asm volatile("cp.async.cg.shared.global [%0],[%1],16;" :: "r"(dst), "l"(src))
#define CPA_COMMIT() asm volatile("cp.async.commit_group;" ::: "memory")
#define CPA_WAIT0()  asm volatile("cp.async.wait_group 0;" ::: "memory")

// ============================================================================
// Attention + fused output projection. BM=128, 8 warps, 2 CTAs/SM.
// Loop tile: S(jt) | exp->P | sync | cp.async QV(jt+1) | PV(jt) | wait | sync
// Epilogue: O/l -> fp16 smem, Wp -> fp16 smem, 128x128 HMMA, +bias -> out.
// ============================================================================
__global__ void __launch_bounds__(256, 2)
attn_mma(const __half* __restrict__ khg, const __half* __restrict__ vhg,
         const __half* __restrict__ qhg, const float* __restrict__ Wp,
         const float* __restrict__ bp, float* __restrict__ out) {
    extern __shared__ char smem[];
    const uint32_t sb = smem_u32(smem);
    const int tid = threadIdx.x, lane = tid & 31, wid = tid >> 5;
    const int q = lane & 3, lr = lane >> 2;
    const int b = blockIdx.y, row0 = blockIdx.x * BM;

    const __half* kh_b = khg + ((size_t)b * NN + row0) * DD;
    const __half* vh_b = vhg + (size_t)b * NN * DD;
    const __half* qh_b = qhg + (size_t)b * NN * DD;

    const int rg = wid >> 1, cg = wid & 1;   // S: 4x2 warp grid (32x32)
    const int r2 = wid >> 2, c2 = wid & 3;   // PV/proj: 2x4 warp grid (64x32)

    const int rA = (lane & 7) + (lane & 8), cA = (lane & 16) >> 1;   // A/P/V pattern
    const int rB = (lane & 7) + ((lane & 16) >> 1), cB = lane & 8;   // B (Q) pattern

    // ldmatrix bases
    uint32_t aK[2], bQ[2], aP[4], bV[2][2];
    #pragma unroll
    for (int mt = 0; mt < 2; ++mt)
        aK[mt] = sb + SM_K + 2u * ((32 * rg + 16 * mt + rA) * 136 + cA);
    #pragma unroll
    for (int bt = 0; bt < 2; ++bt)
        bQ[bt] = sb + SM_Q + 2u * ((32 * cg + 16 * bt + rB) * 136 + cB);
    #pragma unroll
    for (int mt = 0; mt < 4; ++mt)
        aP[mt] = sb + SM_P + 2u * ((64 * r2 + 16 * mt + rA) * 72 + cA);
    #pragma unroll
    for (int bf = 0; bf < 2; ++bf)
        #pragma unroll
        for (int bt = 0; bt < 2; ++bt)
            bV[bf][bt] = sb + SM_V + bf * TBUF +
                         2u * (rA * 136 + 32 * c2 + 16 * bt + cA);

    // stage K tile (resident during main loop)
    #pragma unroll
    for (int t = 0; t < 8; ++t) {
        int c = tid + (t << 8);
        int r = c >> 4, c16 = c & 15;
        *(uint4*)(smem + SM_K + (uint32_t)(r * 272 + c16 * 16)) =
            *(const uint4*)((const char*)(kh_b + (size_t)r * DD) + c16 * 16);
    }
    // prefetch tile 0 (Q, V buf0)
    #pragma unroll
    for (int t = 0; t < 4; ++t) {
        int c = tid + (t << 8);
        int m = c >> 4, c16 = c & 15;
        uint32_t dof = (uint32_t)(m * 272 + c16 * 16);
        CPA16(sb + SM_Q + dof, (const char*)(qh_b + (size_t)m * DD) + c16 * 16);
        CPA16(sb + SM_V + dof, (const char*)(vh_b + (size_t)m * DD) + c16 * 16);
    }
    CPA_COMMIT();
    CPA_WAIT0();
    __syncthreads();   // K + Q(0) + V(0) visible

    float sO[4][4][4];
    #pragma unroll
    for (int i = 0; i < 4; ++i)
        #pragma unroll
        for (int j = 0; j < 4; ++j) {
            sO[i][j][0] = 0.f; sO[i][j][1] = 0.f; sO[i][j][2] = 0.f; sO[i][j][3] = 0.f;
        }
    float lloc[4] = {0.f, 0.f, 0.f, 0.f};

    for (int jt = 0; jt < NT; ++jt) {
        const int vc = jt & 1;

        // ---- S(jt) = K @ Q^T : 32x32 warp tile, 8 k-steps ----
        float sC[2][4][4];
        #pragma unroll
        for (int i = 0; i < 2; ++i)
            #pragma unroll
            for (int j = 0; j < 4; ++j) {
                sC[i][j][0] = 0.f; sC[i][j][1] = 0.f; sC[i][j][2] = 0.f; sC[i][j][3] = 0.f;
            }
        #pragma unroll
        for (int ks = 0; ks < 8; ++ks) {
            uint32_t kf[2][4], qf[2][4];
            #pragma unroll
            for (int mt = 0; mt < 2; ++mt) ldsmx4(kf[mt], aK[mt] + ks * 32);
            #pragma unroll
            for (int bt = 0; bt < 2; ++bt) ldsmx4(qf[bt], bQ[bt] + ks * 32);
            #pragma unroll
            for (int mt = 0; mt < 2; ++mt)
                #pragma unroll
                for (int nt = 0; nt < 4; ++nt)
                    mma16816(sC[mt][nt], kf[mt],
                             qf[nt >> 1][2 * (nt & 1)], qf[nt >> 1][2 * (nt & 1) + 1]);
        }

        // ---- P(jt) = exp2(S) fp16 -> smem; accumulate row sums ----
        #pragma unroll
        for (int mt = 0; mt < 2; ++mt) {
            int rbase = 32 * rg + 16 * mt + lr;
            #pragma unroll
            for (int nt = 0; nt < 4; ++nt) {
                int col = 32 * cg + 8 * nt + 2 * q;
                float p0 = ex2(sC[mt][nt][0]), p1 = ex2(sC[mt][nt][1]);
                float p2 = ex2(sC[mt][nt][2]), p3 = ex2(sC[mt][nt][3]);
                lloc[2 * mt] += p0 + p1;
                lloc[2 * mt + 1] += p2 + p3;
                *(uint32_t*)(smem + SM_P + 2u * (rbase * 72 + col)) = packh2(p0, p1);
                *(uint32_t*)(smem + SM_P + 2u * ((rbase + 8) * 72 + col)) = packh2(p2, p3);
            }
        }
        __syncthreads();   // P visible; Q(jt) fully consumed

        // prefetch Q(jt+1), V(jt+1)
        if (jt + 1 < NT) {
            const size_t m1 = (size_t)(jt + 1) * BN;
            #pragma unroll
            for (int t = 0; t < 4; ++t) {
                int c = tid + (t << 8);
                int m = c >> 4, c16 = c & 15;
                uint32_t dof = (uint32_t)(m * 272 + c16 * 16);
                CPA16(sb + SM_Q + dof,
                      (const char*)(qh_b + (m1 + m) * DD) + c16 * 16);
                CPA16(sb + SM_V + (vc ^ 1) * TBUF + dof,
                      (const char*)(vh_b + (m1 + m) * DD) + c16 * 16);
            }
            CPA_COMMIT();
        }

        // ---- PV(jt): O += P @ V : 64x32 warp tile, 4 k-steps ----
        #pragma unroll
        for (int ks = 0; ks < 4; ++ks) {
            uint32_t ph[4][4], vf[2][4];
            #pragma unroll
            for (int mt = 0; mt < 4; ++mt) ldsmx4(ph[mt], aP[mt] + ks * 32);
            #pragma unroll
            for (int bt = 0; bt < 2; ++bt) ldsmx4t(vf[bt], bV[vc][bt] + ks * 4352);
            #pragma unroll
            for (int mt = 0; mt < 4; ++mt)
                #pragma unroll
                for (int nt = 0; nt < 4; ++nt)
                    mma16816(sO[mt][nt], ph[mt],
                             vf[nt >> 1][2 * (nt & 1)], vf[nt >> 1][2 * (nt & 1) + 1]);
        }

        if (jt + 1 < NT) CPA_WAIT0();
        __syncthreads();   // PV(jt) done; QV(jt+1) arrived
    }

    // ---- l reduction: quad shfl + cross-colgroup via smem ----
    #pragma unroll
    for (int i = 0; i < 4; ++i) {
        lloc[i] += __shfl_xor_sync(0xffffffffu, lloc[i], 1);
        lloc[i] += __shfl_xor_sync(0xffffffffu, lloc[i], 2);
    }
    float* lsum = (float*)(smem + SM_LS);
    if (q == 0) {
        #pragma unroll
        for (int i = 0; i < 4; ++i) {
            int row = 32 * rg + 16 * (i >> 1) + 8 * (i & 1) + lr;
            lsum[cg * 128 + row] = lloc[i];
        }
    }
    __syncthreads();

    // ---- epilogue part 1: O/l -> fp16 into SM_K (pitch 136); Wp -> SM_Q ----
    #pragma unroll
    for (int mt = 0; mt < 4; ++mt) {
        int ra = 64 * r2 + 16 * mt + lr;
        float inva = 1.0f / (lsum[ra] + lsum[128 + ra]);
        float invb = 1.0f / (lsum[ra + 8] + lsum[128 + ra + 8]);
        #pragma unroll
        for (int nt = 0; nt < 4; ++nt) {
            int col = 32 * c2 + 8 * nt + 2 * q;
            *(uint32_t*)(smem + SM_K + 2u * (ra * 136 + col)) =
                packh2(sO[mt][nt][0] * inva, sO[mt][nt][1] * inva);
            *(uint32_t*)(smem + SM_K + 2u * ((ra + 8) * 136 + col)) =
                packh2(sO[mt][nt][2] * invb, sO[mt][nt][3] * invb);
        }
    }
    #pragma unroll
    for (int it = 0; it < 16; ++it) {   // Wp fp32 -> fp16 (pitch 136), [k][n]
        int f = tid + (it << 8);
        int k = f >> 5, c4 = f & 31;
        float4 v = *(const float4*)(Wp + (size_t)k * 128 + (c4 << 2));
        uint2 h; h.x = packh2(v.x, v.y); h.y = packh2(v.z, v.w);
        *(uint2*)(smem + SM_Q + (uint32_t)(k * 272 + (c4 << 3))) = h;
    }
    __syncthreads();

    // ---- epilogue part 2: out = Onorm @ Wp + bp (128x128 HMMA) ----
    {
        uint32_t aB[4], bB[2];
        #pragma unroll
        for (int mt = 0; mt < 4; ++mt)
            aB[mt] = sb + SM_K + 2u * ((64 * r2 + 16 * mt + rA) * 136 + cA);
        #pragma unroll
        for (int bt = 0; bt < 2; ++bt)
            bB[bt] = sb + SM_Q + 2u * (rA * 136 + 32 * c2 + 16 * bt + cA);

        float acc[4][4][4];
        #pragma unroll
        for (int i = 0; i < 4; ++i)
            #pragma unroll
            for (int j = 0; j < 4; ++j) {
                acc[i][j][0] = 0.f; acc[i][j][1] = 0.f; acc[i][j][2] = 0.f; acc[i][j][3] = 0.f;
            }
        #pragma unroll
        for (int ks = 0; ks < 8; ++ks) {
            uint32_t a[4][4], bf[2][4];
            #pragma unroll
            for (int mt = 0; mt < 4; ++mt) ldsmx4(a[mt], aB[mt] + ks * 32);
            #pragma unroll
            for (int bt = 0; bt < 2; ++bt) ldsmx4t(bf[bt], bB[bt] + ks * 4352);
            #pragma unroll
            for (int mt = 0; mt < 4; ++mt)
                #pragma unroll
                for (int nt = 0; nt < 4; ++nt)
                    mma16816(acc[mt][nt], a[mt],
                             bf[nt >> 1][2 * (nt & 1)], bf[nt >> 1][2 * (nt & 1) + 1]);
        }

        float* ob = out + ((size_t)b * NN + row0) * DD;
        #pragma unroll
        for (int mt = 0; mt < 4; ++mt) {
            int ra = 64 * r2 + 16 * mt + lr;
            #pragma unroll
            for (int nt = 0; nt < 4; ++nt) {
                int col = 32 * c2 + 8 * nt + 2 * q;
                float b0 = bp[col], b1 = bp[col + 1];
                *(float2*)(ob + (size_t)ra * DD + col) =
                    make_float2(acc[mt][nt][0] + b0, acc[mt][nt][1] + b1);
                *(float2*)(ob + (size_t)(ra + 8) * DD + col) =
                    make_float2(acc[mt][nt][2] + b0, acc[mt][nt][3] + b1);
            }
        }
    }
}

// ============================================================================
// Q -> fp16 (pre-scaled by SCALE*log2e)
// ============================================================================
__global__ void __launch_bounds__(256)
qconv_kernel(const float* __restrict__ qg, __half* __restrict__ qh) {
    int i = blockIdx.x * 256 + threadIdx.x;
    float4 v = ((const float4*)qg)[i];
    ((__half2*)qh)[2 * i]     = __floats2half2_rn(v.x * QS, v.y * QS);
    ((__half2*)qh)[2 * i + 1] = __floats2half2_rn(v.z * QS, v.w * QS);
}

// ============================================================================
// fp16 tensor-core kv projection (128x128 CTA tile, K=128 resident)
// ============================================================================
__device__ __forceinline__ uint32_t pack_us2(__half a, __half b) {
    return (uint32_t)__half_as_ushort(a) | ((uint32_t)__half_as_ushort(b) << 16);
}

__global__ void __launch_bounds__(256, 2)
gemm16_kv(const float* __restrict__ A, const float* __restrict__ W,
          const float* __restrict__ bias,
          __half* __restrict__ kh, __half* __restrict__ vh) {
    extern __shared__ char smg[];
    const uint32_t sb = smem_u32(smg);
    const int tid = threadIdx.x, lane = tid & 31, wid = tid >> 5;
    const int q = lane & 3, lr = lane >> 2;
    const int rw = wid >> 2, cw = wid & 3;
    const int row0 = blockIdx.y * 128, col0 = blockIdx.x * 128;

    #pragma unroll
    for (int it = 0; it < 16; ++it) {
        int f = tid + (it << 8);
        int r = f >> 5, c4 = f & 31;
        float4 v = *(const float4*)(A + (size_t)(row0 + r) * 128 + (c4 << 2));
        uint2 h; h.x = packh2(v.x, v.y); h.y = packh2(v.z, v.w);
        *(uint2*)(smg + (uint32_t)(r * 272 + (c4 << 3))) = h;
    }
    #pragma unroll
    for (int it = 0; it < 16; ++it) {
        int f = tid + (it << 8);
        int k = f >> 5, c4 = f & 31;
        float4 v = *(const float4*)(W + (size_t)k * 256 + col0 + (c4 << 2));
        uint2 h; h.x = packh2(v.x, v.y); h.y = packh2(v.z, v.w);
        *(uint2*)(smg + 34816 + (uint32_t)(k * 272 + (c4 << 3))) = h;
    }
    __syncthreads();

    const int rA = (lane & 7) + (lane & 8), cA = (lane & 16) >> 1;
    uint32_t aBase[4], bBase[2];
    #pragma unroll
    for (int mt = 0; mt < 4; ++mt)
        aBase[mt] = sb + 2u * ((64 * rw + 16 * mt + rA) * 136 + cA);
    #pragma unroll
    for (int bt = 0; bt < 2; ++bt)
        bBase[bt] = sb + 34816 + 2u * (rA * 136 + 32 * cw + 16 * bt + cA);

    float acc[4][4][4];
    #pragma unroll
    for (int i = 0; i < 4; ++i)
        #pragma unroll
        for (int j = 0; j < 4; ++j) {
            acc[i][j][0] = 0.f; acc[i][j][1] = 0.f; acc[i][j][2] = 0.f; acc[i][j][3] = 0.f;
        }
    #pragma unroll
    for (int ks = 0; ks < 8; ++ks) {
        uint32_t a[4][4], bf[2][4];
        #pragma unroll
        for (int mt = 0; mt < 4; ++mt) ldsmx4(a[mt], aBase[mt] + ks * 32);
        #pragma unroll
        for (int bt = 0; bt < 2; ++bt) ldsmx4t(bf[bt], bBase[bt] + ks * 4352);
        #pragma unroll
        for (int mt = 0; mt < 4; ++mt)
            #pragma unroll
            for (int nt = 0; nt < 4; ++nt)
                mma16816(acc[mt][nt], a[mt],
                         bf[nt >> 1][2 * (nt & 1)], bf[nt >> 1][2 * (nt & 1) + 1]);
    }

    __half* dh = (col0 == 0) ? kh : vh;
    #pragma unroll
    for (int mt = 0; mt < 4; ++mt) {
        int r = row0 + 64 * rw + 16 * mt + lr;
        #pragma unroll
        for (int nt = 0; nt < 4; ++nt) {
            int col = 32 * cw + 8 * nt + 2 * q;
            float b0 = bias[col0 + col], b1 = bias[col0 + col + 1];
            *(uint32_t*)(dh + (size_t)r * 128 + col) = pack_us2(
                __float2half_rn(acc[mt][nt][0] + b0), __float2half_rn(acc[mt][nt][1] + b1));
            *(uint32_t*)(dh + (size_t)(r + 8) * 128 + col) = pack_us2(
                __float2half_rn(acc[mt][nt][2] + b0), __float2half_rn(acc[mt][nt][3] + b1));
        }
    }
}

// ============================================================================
extern "C" void kernel_launch(void* const* d_in, const int* in_sizes, int n_in,
                              void* d_out, int out_size) {
    const float* x   = (const float*)d_in[0];
    const float* qg  = (const float*)d_in[1];
    const float* Wkv = (const float*)d_in[2];
    const float* bkv = (const float*)d_in[3];
    const float* Wp  = (const float*)d_in[4];
    const float* bp  = (const float*)d_in[5];
    float* out = (float*)d_out;

    __half *khp, *vhp, *qhp;
    cudaGetSymbolAddress((void**)&khp, g_kh);
    cudaGetSymbolAddress((void**)&vhp, g_vh);
    cudaGetSymbolAddress((void**)&qhp, g_qh);

    const int M = BB * NN;
    const int gsm = 2 * 128 * 272;  // 69632 B

    cudaFuncSetAttribute(gemm16_kv,
                         cudaFuncAttributeMaxDynamicSharedMemorySize, gsm);
    cudaFuncSetAttribute(attn_mma,
                         cudaFuncAttributeMaxDynamicSharedMemorySize, SM_TOT);

    gemm16_kv<<<dim3(2, M / 128), 256, gsm>>>(x, Wkv, bkv, khp, vhp);
    qconv_kernel<<<(M * DD / 4) / 256, 256>>>(qg, qhp);
    attn_mma<<<dim3(NN / BM, BB), 256, SM_TOT>>>(khp, vhp, qhp, Wp, bp, out);
}